// round 10
// baseline (speedup 1.0000x reference)
#include <cuda_runtime.h>
#include <math.h>

#define W_IMG 1024
#define N_PIX (W_IMG * W_IMG)
#define MAXB 8
#define NTH 256
#define NBLK_STAT 512   // 8 x 64 blocks per batch

// per-block partial stats: [b][block][16]
// [0..2]=sum q_c^2, [3..5]=sum k_c^2, [6..14]=sum q_c*k_d
__device__ float g_part[MAXB][NBLK_STAT][16];
__device__ float g_M[MAXB][12];
__device__ int   g_cnt[MAXB];   // zero-init at load; finalizer resets each launch

// ---------------------------------------------------------------------------
// k_stats: 4-wide x 2-tall patch per thread. K path first (kout in regs),
// then Q path. Per-block partials + last-block finalize computing g_M.
// ---------------------------------------------------------------------------
__global__ __launch_bounds__(NTH, 2) void k_stats(const float* __restrict__ x,
                                                  const float* __restrict__ fhigh,
                                                  const float* __restrict__ qC,
                                                  const float* __restrict__ qD,
                                                  const float* __restrict__ kC,
                                                  const float* __restrict__ kD,
                                                  const float* __restrict__ proj_w,
                                                  const float* __restrict__ temp) {
    __shared__ float red[NTH / 32][15];
    __shared__ int sflag;

    const int tid = threadIdx.x;
    const int b = blockIdx.z;
    const int warp = tid >> 5, lane = tid & 31;
    const int wx0 = blockIdx.x * 128;
    const int px0 = wx0 + lane * 4;
    const int y0 = blockIdx.y * 16 + warp * 2;   // 2 output rows per warp

    const float* __restrict__ xb = x + (size_t)b * 3 * N_PIX;
    const float* __restrict__ fb = fhigh + (size_t)b * 3 * N_PIX;

    const bool is_e = (lane == 0) | (lane == 31);
    const int ex = (lane == 0) ? wx0 - 1 : wx0 + 128;
    const bool ex_ok = (unsigned)ex < (unsigned)W_IMG;

    float p[15];
#pragma unroll
    for (int i = 0; i < 15; i++) p[i] = 0.f;

    float kout[3][2][4];  // [ch][row][j]

    // ================= K path (input x, channels-last) =================
    {
        float cw[9], dw[27];
#pragma unroll
        for (int i = 0; i < 9; i++) cw[i] = kC[i];
#pragma unroll
        for (int i = 0; i < 27; i++) dw[i] = kD[i];

        float a0[3][4], a1[3][4], a2[3][4];
#pragma unroll
        for (int c = 0; c < 3; c++)
#pragma unroll
            for (int j = 0; j < 4; j++) { a0[c][j] = a1[c][j] = a2[c][j] = 0.f; }

#pragma unroll
        for (int iy = 0; iy < 4; iy++) {
            const int yin = y0 + iy - 1;
            const bool yok = (unsigned)yin < (unsigned)W_IMG;

            float hm[3][4];
#pragma unroll
            for (int c = 0; c < 3; c++)
#pragma unroll
                for (int j = 0; j < 4; j++) hm[c][j] = 0.f;

            if (yok) {
                const float4* p4 = (const float4*)(xb + (size_t)(yin * W_IMG + px0) * 3);
                float4 v0 = p4[0], v1 = p4[1], v2 = p4[2];
                float g[4][3] = {{v0.x, v0.y, v0.z}, {v0.w, v1.x, v1.y},
                                 {v1.z, v1.w, v2.x}, {v2.y, v2.z, v2.w}};
#pragma unroll
                for (int j = 0; j < 4; j++)
#pragma unroll
                    for (int c = 0; c < 3; c++)
                        hm[c][j] = cw[c * 3] * g[j][0] + cw[c * 3 + 1] * g[j][1] + cw[c * 3 + 2] * g[j][2];
            }
            float he[3] = {0.f, 0.f, 0.f};
            if (yok && is_e && ex_ok) {
                const float* pe = xb + (size_t)(yin * W_IMG + ex) * 3;
                float g0 = pe[0], g1 = pe[1], g2 = pe[2];
#pragma unroll
                for (int c = 0; c < 3; c++)
                    he[c] = cw[c * 3] * g0 + cw[c * 3 + 1] * g1 + cw[c * 3 + 2] * g2;
            }
            float hl[3], hr[3];
#pragma unroll
            for (int c = 0; c < 3; c++) {
                hl[c] = __shfl_up_sync(0xffffffffu, hm[c][3], 1);
                hr[c] = __shfl_down_sync(0xffffffffu, hm[c][0], 1);
                if (lane == 0) hl[c] = he[c];
                if (lane == 31) hr[c] = he[c];
            }
#pragma unroll
            for (int c = 0; c < 3; c++)
#pragma unroll
                for (int j = 0; j < 4; j++) {
                    float L = j ? hm[c][j - 1] : hl[c];
                    float M_ = hm[c][j];
                    float R = (j < 3) ? hm[c][j + 1] : hr[c];
                    a0[c][j] += dw[c * 9 + 6] * L + dw[c * 9 + 7] * M_ + dw[c * 9 + 8] * R;
                    a1[c][j] += dw[c * 9 + 3] * L + dw[c * 9 + 4] * M_ + dw[c * 9 + 5] * R;
                    a2[c][j] += dw[c * 9 + 0] * L + dw[c * 9 + 1] * M_ + dw[c * 9 + 2] * R;
                }
            if (iy >= 2) {
                const int r = iy - 2;
#pragma unroll
                for (int c = 0; c < 3; c++)
#pragma unroll
                    for (int j = 0; j < 4; j++) {
                        float v = a0[c][j];
                        kout[c][r][j] = v;
                        p[3 + c] += v * v;
                    }
            }
#pragma unroll
            for (int c = 0; c < 3; c++)
#pragma unroll
                for (int j = 0; j < 4; j++) {
                    a0[c][j] = a1[c][j];
                    a1[c][j] = a2[c][j];
                    a2[c][j] = 0.f;
                }
        }
    }

    // ================= Q path (input fhigh, planar) =================
    {
        float cw[9], dw[27];
#pragma unroll
        for (int i = 0; i < 9; i++) cw[i] = qC[i];
#pragma unroll
        for (int i = 0; i < 27; i++) dw[i] = qD[i];

        float a0[3][4], a1[3][4], a2[3][4];
#pragma unroll
        for (int c = 0; c < 3; c++)
#pragma unroll
            for (int j = 0; j < 4; j++) { a0[c][j] = a1[c][j] = a2[c][j] = 0.f; }

#pragma unroll
        for (int iy = 0; iy < 4; iy++) {
            const int yin = y0 + iy - 1;
            const bool yok = (unsigned)yin < (unsigned)W_IMG;

            float hm[3][4];
#pragma unroll
            for (int c = 0; c < 3; c++)
#pragma unroll
                for (int j = 0; j < 4; j++) hm[c][j] = 0.f;

            if (yok) {
                const size_t o = (size_t)yin * W_IMG + px0;
                float4 f0 = *(const float4*)(fb + o);
                float4 f1 = *(const float4*)(fb + o + N_PIX);
                float4 f2 = *(const float4*)(fb + o + 2 * N_PIX);
                float g[4][3] = {{f0.x, f1.x, f2.x}, {f0.y, f1.y, f2.y},
                                 {f0.z, f1.z, f2.z}, {f0.w, f1.w, f2.w}};
#pragma unroll
                for (int j = 0; j < 4; j++)
#pragma unroll
                    for (int c = 0; c < 3; c++)
                        hm[c][j] = cw[c * 3] * g[j][0] + cw[c * 3 + 1] * g[j][1] + cw[c * 3 + 2] * g[j][2];
            }
            float he[3] = {0.f, 0.f, 0.f};
            if (yok && is_e && ex_ok) {
                const size_t o = (size_t)yin * W_IMG + ex;
                float g0 = fb[o], g1 = fb[o + N_PIX], g2 = fb[o + 2 * N_PIX];
#pragma unroll
                for (int c = 0; c < 3; c++)
                    he[c] = cw[c * 3] * g0 + cw[c * 3 + 1] * g1 + cw[c * 3 + 2] * g2;
            }
            float hl[3], hr[3];
#pragma unroll
            for (int c = 0; c < 3; c++) {
                hl[c] = __shfl_up_sync(0xffffffffu, hm[c][3], 1);
                hr[c] = __shfl_down_sync(0xffffffffu, hm[c][0], 1);
                if (lane == 0) hl[c] = he[c];
                if (lane == 31) hr[c] = he[c];
            }
#pragma unroll
            for (int c = 0; c < 3; c++)
#pragma unroll
                for (int j = 0; j < 4; j++) {
                    float L = j ? hm[c][j - 1] : hl[c];
                    float M_ = hm[c][j];
                    float R = (j < 3) ? hm[c][j + 1] : hr[c];
                    a0[c][j] += dw[c * 9 + 6] * L + dw[c * 9 + 7] * M_ + dw[c * 9 + 8] * R;
                    a1[c][j] += dw[c * 9 + 3] * L + dw[c * 9 + 4] * M_ + dw[c * 9 + 5] * R;
                    a2[c][j] += dw[c * 9 + 0] * L + dw[c * 9 + 1] * M_ + dw[c * 9 + 2] * R;
                }
            if (iy >= 2) {
                const int r = iy - 2;
#pragma unroll
                for (int c = 0; c < 3; c++)
#pragma unroll
                    for (int j = 0; j < 4; j++) {
                        float q = a0[c][j];
                        p[c] += q * q;
#pragma unroll
                        for (int d = 0; d < 3; d++)
                            p[6 + c * 3 + d] += q * kout[d][r][j];
                    }
            }
#pragma unroll
            for (int c = 0; c < 3; c++)
#pragma unroll
                for (int j = 0; j < 4; j++) {
                    a0[c][j] = a1[c][j];
                    a1[c][j] = a2[c][j];
                    a2[c][j] = 0.f;
                }
        }
    }

    // block reduce -> per-block partial
#pragma unroll
    for (int i = 0; i < 15; i++)
#pragma unroll
        for (int o = 16; o; o >>= 1)
            p[i] += __shfl_down_sync(0xffffffffu, p[i], o);
    if (lane == 0) {
#pragma unroll
        for (int i = 0; i < 15; i++) red[warp][i] = p[i];
    }
    __syncthreads();
    if (tid < 15) {
        float t = 0.f;
#pragma unroll
        for (int w2 = 0; w2 < NTH / 32; w2++) t += red[w2][tid];
        g_part[b][blockIdx.y * 8 + blockIdx.x][tid] = t;
    } else if (tid == 16) {
        g_part[b][blockIdx.y * 8 + blockIdx.x][15] = 0.f;
    }
    __syncthreads();

    // --- last-block finalize ---
    if (tid == 0) {
        __threadfence();
        int v = atomicAdd(&g_cnt[b], 1);
        sflag = (v == NBLK_STAT - 1);
    }
    __syncthreads();
    if (sflag) {
        __threadfence();
        float q[15];
        const float4* rowA = (const float4*)g_part[b][tid];
        const float4* rowB = (const float4*)g_part[b][tid + 256];
        float4 a0 = rowA[0], a1 = rowA[1], a2 = rowA[2], a3 = rowA[3];
        float4 b0 = rowB[0], b1 = rowB[1], b2 = rowB[2], b3 = rowB[3];
        q[0] = a0.x + b0.x;  q[1] = a0.y + b0.y;  q[2] = a0.z + b0.z;  q[3] = a0.w + b0.w;
        q[4] = a1.x + b1.x;  q[5] = a1.y + b1.y;  q[6] = a1.z + b1.z;  q[7] = a1.w + b1.w;
        q[8] = a2.x + b2.x;  q[9] = a2.y + b2.y;  q[10] = a2.z + b2.z; q[11] = a2.w + b2.w;
        q[12] = a3.x + b3.x; q[13] = a3.y + b3.y; q[14] = a3.z + b3.z;
#pragma unroll
        for (int i = 0; i < 15; i++)
#pragma unroll
            for (int o = 16; o; o >>= 1)
                q[i] += __shfl_down_sync(0xffffffffu, q[i], o);
        if (lane == 0) {
#pragma unroll
            for (int i = 0; i < 15; i++) red[warp][i] = q[i];
        }
        __syncthreads();
        if (tid == 0) {
            float ss[15];
#pragma unroll
            for (int i = 0; i < 15; i++) {
                float t = 0.f;
#pragma unroll
                for (int w2 = 0; w2 < NTH / 32; w2++) t += red[w2][i];
                ss[i] = t;
            }
            float T = temp[0];
            float nq[3], nk[3];
#pragma unroll
            for (int c = 0; c < 3; c++) {
                nq[c] = fmaxf(sqrtf(ss[c]), 1e-12f);
                nk[c] = fmaxf(sqrtf(ss[3 + c]), 1e-12f);
            }
            float a[3][3];
#pragma unroll
            for (int c = 0; c < 3; c++)
#pragma unroll
                for (int d = 0; d < 3; d++)
                    a[c][d] = ss[6 + c * 3 + d] / (nq[c] * nk[d]) * T;
#pragma unroll
            for (int c = 0; c < 3; c++) {
                float mx = fmaxf(a[c][0], fmaxf(a[c][1], a[c][2]));
                float e0 = expf(a[c][0] - mx);
                float e1 = expf(a[c][1] - mx);
                float e2 = expf(a[c][2] - mx);
                float inv = 1.f / (e0 + e1 + e2);
                a[c][0] = e0 * inv; a[c][1] = e1 * inv; a[c][2] = e2 * inv;
            }
#pragma unroll
            for (int co = 0; co < 3; co++)
#pragma unroll
                for (int d = 0; d < 3; d++) {
                    float mm = 0.f;
#pragma unroll
                    for (int c = 0; c < 3; c++) mm += proj_w[co * 3 + c] * a[c][d];
                    g_M[b][co * 3 + d] = mm;
                }
            g_cnt[b] = 0;   // reset for next graph replay
            __threadfence();
        }
    }
}

// ---------------------------------------------------------------------------
// k_out: R4-proven 4x4 patch version; reads g_M broadcast (L2-hot).
// ---------------------------------------------------------------------------
__global__ __launch_bounds__(NTH) void k_out(const float* __restrict__ x,
                                             const float* __restrict__ kC,
                                             const float* __restrict__ kD,
                                             const float* __restrict__ proj_b,
                                             float* __restrict__ out) {
    const int b = blockIdx.z;
    const int warp = threadIdx.x >> 5, lane = threadIdx.x & 31;
    const int wx0 = blockIdx.x * 128;
    const int px0 = wx0 + lane * 4;
    const int y0 = blockIdx.y * 32 + warp * 4;

    const float* __restrict__ xb = x + (size_t)b * 3 * N_PIX;

    const bool is_e = (lane == 0) | (lane == 31);
    const int ex = (lane == 0) ? wx0 - 1 : wx0 + 128;
    const bool ex_ok = (unsigned)ex < (unsigned)W_IMG;

    float cw[9], dw[27];
#pragma unroll
    for (int i = 0; i < 9; i++) cw[i] = kC[i];
#pragma unroll
    for (int i = 0; i < 27; i++) dw[i] = kD[i];

    float m[9];
#pragma unroll
    for (int i = 0; i < 9; i++) m[i] = g_M[b][i];
    const float b0 = proj_b[0], b1 = proj_b[1], b2 = proj_b[2];

    float a0[3][4], a1[3][4], a2[3][4];
#pragma unroll
    for (int c = 0; c < 3; c++)
#pragma unroll
        for (int j = 0; j < 4; j++) { a0[c][j] = a1[c][j] = a2[c][j] = 0.f; }

#pragma unroll
    for (int iy = 0; iy < 6; iy++) {
        const int yin = y0 + iy - 1;
        const bool yok = (unsigned)yin < (unsigned)W_IMG;

        float hm[3][4];
#pragma unroll
        for (int c = 0; c < 3; c++)
#pragma unroll
            for (int j = 0; j < 4; j++) hm[c][j] = 0.f;

        if (yok) {
            const float4* p4 = (const float4*)(xb + (size_t)(yin * W_IMG + px0) * 3);
            float4 v0 = p4[0], v1 = p4[1], v2 = p4[2];
            float g[4][3] = {{v0.x, v0.y, v0.z}, {v0.w, v1.x, v1.y},
                             {v1.z, v1.w, v2.x}, {v2.y, v2.z, v2.w}};
#pragma unroll
            for (int j = 0; j < 4; j++)
#pragma unroll
                for (int c = 0; c < 3; c++)
                    hm[c][j] = cw[c * 3] * g[j][0] + cw[c * 3 + 1] * g[j][1] + cw[c * 3 + 2] * g[j][2];
        }
        float he[3] = {0.f, 0.f, 0.f};
        if (yok && is_e && ex_ok) {
            const float* pe = xb + (size_t)(yin * W_IMG + ex) * 3;
            float g0 = pe[0], g1 = pe[1], g2 = pe[2];
#pragma unroll
            for (int c = 0; c < 3; c++)
                he[c] = cw[c * 3] * g0 + cw[c * 3 + 1] * g1 + cw[c * 3 + 2] * g2;
        }
        float hl[3], hr[3];
#pragma unroll
        for (int c = 0; c < 3; c++) {
            hl[c] = __shfl_up_sync(0xffffffffu, hm[c][3], 1);
            hr[c] = __shfl_down_sync(0xffffffffu, hm[c][0], 1);
            if (lane == 0) hl[c] = he[c];
            if (lane == 31) hr[c] = he[c];
        }
#pragma unroll
        for (int c = 0; c < 3; c++)
#pragma unroll
            for (int j = 0; j < 4; j++) {
                float L = j ? hm[c][j - 1] : hl[c];
                float M_ = hm[c][j];
                float R = (j < 3) ? hm[c][j + 1] : hr[c];
                a0[c][j] += dw[c * 9 + 6] * L + dw[c * 9 + 7] * M_ + dw[c * 9 + 8] * R;
                a1[c][j] += dw[c * 9 + 3] * L + dw[c * 9 + 4] * M_ + dw[c * 9 + 5] * R;
                a2[c][j] += dw[c * 9 + 0] * L + dw[c * 9 + 1] * M_ + dw[c * 9 + 2] * R;
            }
        if (iy >= 2) {
            const int yout = y0 + iy - 2;
            float o[12];
#pragma unroll
            for (int j = 0; j < 4; j++) {
                float k0 = a0[0][j], k1 = a0[1][j], k2 = a0[2][j];
                o[j * 3 + 0] = m[0] * k0 + m[1] * k1 + m[2] * k2 + b0;
                o[j * 3 + 1] = m[3] * k0 + m[4] * k1 + m[5] * k2 + b1;
                o[j * 3 + 2] = m[6] * k0 + m[7] * k1 + m[8] * k2 + b2;
            }
            float4* q4 = (float4*)(out + ((size_t)b * N_PIX + (size_t)yout * W_IMG + px0) * 3);
            q4[0] = make_float4(o[0], o[1], o[2], o[3]);
            q4[1] = make_float4(o[4], o[5], o[6], o[7]);
            q4[2] = make_float4(o[8], o[9], o[10], o[11]);
        }
#pragma unroll
        for (int c = 0; c < 3; c++)
#pragma unroll
            for (int j = 0; j < 4; j++) {
                a0[c][j] = a1[c][j];
                a1[c][j] = a2[c][j];
                a2[c][j] = 0.f;
            }
    }
}

extern "C" void kernel_launch(void* const* d_in, const int* in_sizes, int n_in,
                              void* d_out, int out_size) {
    const float* x     = (const float*)d_in[0];
    const float* fhigh = (const float*)d_in[1];
    const float* qCw   = (const float*)d_in[2];
    const float* qdw   = (const float*)d_in[3];
    const float* kCw   = (const float*)d_in[4];
    const float* kdw   = (const float*)d_in[5];
    const float* projw = (const float*)d_in[6];
    const float* projb = (const float*)d_in[7];
    const float* temp  = (const float*)d_in[8];
    float* out = (float*)d_out;

    int B = in_sizes[0] / (N_PIX * 3);
    if (B > MAXB) B = MAXB;

    dim3 gridS(W_IMG / 128, W_IMG / 16, B);   // 8 x 64 = 512 blocks per batch
    k_stats<<<gridS, NTH>>>(x, fhigh, qCw, qdw, kCw, kdw, projw, temp);
    dim3 gridO(W_IMG / 128, W_IMG / 32, B);   // 8 x 32 = 256 blocks per batch
    k_out<<<gridO, NTH>>>(x, kCw, kdw, projb, out);
}

// round 11
// speedup vs baseline: 1.0777x; 1.0777x over previous
#include <cuda_runtime.h>
#include <math.h>

#define W_IMG 1024
#define N_PIX (W_IMG * W_IMG)
#define MAXB 8
#define NTH 256
#define NBLK_STAT 32    // 8 x 4 blocks per batch

// per-block partial stats: [b][block][16]
// [0..2]=sum q_c^2, [3..5]=sum k_c^2, [6..14]=sum q_c*k_d
__device__ float g_part[MAXB][NBLK_STAT][16];
__device__ float g_M[MAXB][12];
__device__ int   g_cnt[MAXB];   // zero-init at load; finalizer resets each launch

// ---------------------------------------------------------------------------
// k_stats: interleaved k/q paths, 4-wide x 32-tall warp strip (34 input rows,
// halo overhead 1.06x). No kout patch: stats accumulate on the fly.
// Per-block partials + last-block warp finalize computing g_M.
// ---------------------------------------------------------------------------
__global__ __launch_bounds__(NTH) void k_stats(const float* __restrict__ x,
                                               const float* __restrict__ fhigh,
                                               const float* __restrict__ qC,
                                               const float* __restrict__ qD,
                                               const float* __restrict__ kC,
                                               const float* __restrict__ kD,
                                               const float* __restrict__ proj_w,
                                               const float* __restrict__ temp) {
    __shared__ float red[NTH / 32][15];
    __shared__ int sflag;

    const int tid = threadIdx.x;
    const int b = blockIdx.z;
    const int warp = tid >> 5, lane = tid & 31;
    const int wx0 = blockIdx.x * 128;
    const int px0 = wx0 + lane * 4;
    const int y0 = (blockIdx.y * 8 + warp) * 32;   // 32-row strip per warp

    const float* __restrict__ xb = x + (size_t)b * 3 * N_PIX;
    const float* __restrict__ fb = fhigh + (size_t)b * 3 * N_PIX;

    const bool is_e = (lane == 0) | (lane == 31);
    const int ex = (lane == 0) ? wx0 - 1 : wx0 + 128;
    const bool ex_ok = (unsigned)ex < (unsigned)W_IMG;

    float kcw[9], kdw[27], qcw[9], qdw[27];
#pragma unroll
    for (int i = 0; i < 9; i++) { kcw[i] = kC[i]; qcw[i] = qC[i]; }
#pragma unroll
    for (int i = 0; i < 27; i++) { kdw[i] = kD[i]; qdw[i] = qD[i]; }

    float p[15];
#pragma unroll
    for (int i = 0; i < 15; i++) p[i] = 0.f;

    float ka0[3][4], ka1[3][4], ka2[3][4];
    float qa0[3][4], qa1[3][4], qa2[3][4];
#pragma unroll
    for (int c = 0; c < 3; c++)
#pragma unroll
        for (int j = 0; j < 4; j++) {
            ka0[c][j] = ka1[c][j] = ka2[c][j] = 0.f;
            qa0[c][j] = qa1[c][j] = qa2[c][j] = 0.f;
        }

#pragma unroll 2
    for (int iy = 0; iy < 34; ++iy) {
        const int yin = y0 + iy - 1;
        const bool yok = (unsigned)yin < (unsigned)W_IMG;

        float khm[3][4], qhm[3][4];
#pragma unroll
        for (int c = 0; c < 3; c++)
#pragma unroll
            for (int j = 0; j < 4; j++) { khm[c][j] = 0.f; qhm[c][j] = 0.f; }

        if (yok) {
            // k path input: x channels-last
            const float4* p4 = (const float4*)(xb + (size_t)(yin * W_IMG + px0) * 3);
            float4 v0 = p4[0], v1 = p4[1], v2 = p4[2];
            float gk[4][3] = {{v0.x, v0.y, v0.z}, {v0.w, v1.x, v1.y},
                              {v1.z, v1.w, v2.x}, {v2.y, v2.z, v2.w}};
            // q path input: fhigh planar
            const size_t o = (size_t)yin * W_IMG + px0;
            float4 f0 = *(const float4*)(fb + o);
            float4 f1 = *(const float4*)(fb + o + N_PIX);
            float4 f2 = *(const float4*)(fb + o + 2 * N_PIX);
            float gq[4][3] = {{f0.x, f1.x, f2.x}, {f0.y, f1.y, f2.y},
                              {f0.z, f1.z, f2.z}, {f0.w, f1.w, f2.w}};
#pragma unroll
            for (int j = 0; j < 4; j++)
#pragma unroll
                for (int c = 0; c < 3; c++) {
                    khm[c][j] = kcw[c * 3] * gk[j][0] + kcw[c * 3 + 1] * gk[j][1] + kcw[c * 3 + 2] * gk[j][2];
                    qhm[c][j] = qcw[c * 3] * gq[j][0] + qcw[c * 3 + 1] * gq[j][1] + qcw[c * 3 + 2] * gq[j][2];
                }
        }
        float khe[3] = {0.f, 0.f, 0.f}, qhe[3] = {0.f, 0.f, 0.f};
        if (yok && is_e && ex_ok) {
            const float* pe = xb + (size_t)(yin * W_IMG + ex) * 3;
            float g0 = pe[0], g1 = pe[1], g2 = pe[2];
            const size_t o = (size_t)yin * W_IMG + ex;
            float h0 = fb[o], h1 = fb[o + N_PIX], h2 = fb[o + 2 * N_PIX];
#pragma unroll
            for (int c = 0; c < 3; c++) {
                khe[c] = kcw[c * 3] * g0 + kcw[c * 3 + 1] * g1 + kcw[c * 3 + 2] * g2;
                qhe[c] = qcw[c * 3] * h0 + qcw[c * 3 + 1] * h1 + qcw[c * 3 + 2] * h2;
            }
        }
#pragma unroll
        for (int c = 0; c < 3; c++) {
            float kl = __shfl_up_sync(0xffffffffu, khm[c][3], 1);
            float kr = __shfl_down_sync(0xffffffffu, khm[c][0], 1);
            float ql = __shfl_up_sync(0xffffffffu, qhm[c][3], 1);
            float qr = __shfl_down_sync(0xffffffffu, qhm[c][0], 1);
            if (lane == 0)  { kl = khe[c]; ql = qhe[c]; }
            if (lane == 31) { kr = khe[c]; qr = qhe[c]; }
#pragma unroll
            for (int j = 0; j < 4; j++) {
                float KL = j ? khm[c][j - 1] : kl;
                float KM = khm[c][j];
                float KR = (j < 3) ? khm[c][j + 1] : kr;
                ka0[c][j] += kdw[c * 9 + 6] * KL + kdw[c * 9 + 7] * KM + kdw[c * 9 + 8] * KR;
                ka1[c][j] += kdw[c * 9 + 3] * KL + kdw[c * 9 + 4] * KM + kdw[c * 9 + 5] * KR;
                ka2[c][j] += kdw[c * 9 + 0] * KL + kdw[c * 9 + 1] * KM + kdw[c * 9 + 2] * KR;
                float QL = j ? qhm[c][j - 1] : ql;
                float QM = qhm[c][j];
                float QR = (j < 3) ? qhm[c][j + 1] : qr;
                qa0[c][j] += qdw[c * 9 + 6] * QL + qdw[c * 9 + 7] * QM + qdw[c * 9 + 8] * QR;
                qa1[c][j] += qdw[c * 9 + 3] * QL + qdw[c * 9 + 4] * QM + qdw[c * 9 + 5] * QR;
                qa2[c][j] += qdw[c * 9 + 0] * QL + qdw[c * 9 + 1] * QM + qdw[c * 9 + 2] * QR;
            }
        }
        if (iy >= 2) {
#pragma unroll
            for (int j = 0; j < 4; j++) {
                float k0 = ka0[0][j], k1 = ka0[1][j], k2 = ka0[2][j];
                float q0 = qa0[0][j], q1 = qa0[1][j], q2 = qa0[2][j];
                p[0] += q0 * q0; p[1] += q1 * q1; p[2] += q2 * q2;
                p[3] += k0 * k0; p[4] += k1 * k1; p[5] += k2 * k2;
                p[6]  += q0 * k0; p[7]  += q0 * k1; p[8]  += q0 * k2;
                p[9]  += q1 * k0; p[10] += q1 * k1; p[11] += q1 * k2;
                p[12] += q2 * k0; p[13] += q2 * k1; p[14] += q2 * k2;
            }
        }
#pragma unroll
        for (int c = 0; c < 3; c++)
#pragma unroll
            for (int j = 0; j < 4; j++) {
                ka0[c][j] = ka1[c][j]; ka1[c][j] = ka2[c][j]; ka2[c][j] = 0.f;
                qa0[c][j] = qa1[c][j]; qa1[c][j] = qa2[c][j]; qa2[c][j] = 0.f;
            }
    }

    // block reduce -> per-block partial
#pragma unroll
    for (int i = 0; i < 15; i++)
#pragma unroll
        for (int o = 16; o; o >>= 1)
            p[i] += __shfl_down_sync(0xffffffffu, p[i], o);
    if (lane == 0) {
#pragma unroll
        for (int i = 0; i < 15; i++) red[warp][i] = p[i];
    }
    __syncthreads();
    const int bi = blockIdx.y * 8 + blockIdx.x;
    if (tid < 15) {
        float t = 0.f;
#pragma unroll
        for (int w2 = 0; w2 < NTH / 32; w2++) t += red[w2][tid];
        g_part[b][bi][tid] = t;
    }
    __syncthreads();

    // --- last-block finalize (32 partials = exactly one warp) ---
    if (tid == 0) {
        __threadfence();
        int v = atomicAdd(&g_cnt[b], 1);
        sflag = (v == NBLK_STAT - 1);
    }
    __syncthreads();
    if (sflag && warp == 0) {
        __threadfence();
        float q[15];
#pragma unroll
        for (int i = 0; i < 15; i++) q[i] = g_part[b][lane][i];
#pragma unroll
        for (int i = 0; i < 15; i++)
#pragma unroll
            for (int o = 16; o; o >>= 1)
                q[i] += __shfl_down_sync(0xffffffffu, q[i], o);
        if (lane == 0) {
            float T = temp[0];
            float nq[3], nk[3];
#pragma unroll
            for (int c = 0; c < 3; c++) {
                nq[c] = fmaxf(sqrtf(q[c]), 1e-12f);
                nk[c] = fmaxf(sqrtf(q[3 + c]), 1e-12f);
            }
            float a[3][3];
#pragma unroll
            for (int c = 0; c < 3; c++)
#pragma unroll
                for (int d = 0; d < 3; d++)
                    a[c][d] = q[6 + c * 3 + d] / (nq[c] * nk[d]) * T;
#pragma unroll
            for (int c = 0; c < 3; c++) {
                float mx = fmaxf(a[c][0], fmaxf(a[c][1], a[c][2]));
                float e0 = expf(a[c][0] - mx);
                float e1 = expf(a[c][1] - mx);
                float e2 = expf(a[c][2] - mx);
                float inv = 1.f / (e0 + e1 + e2);
                a[c][0] = e0 * inv; a[c][1] = e1 * inv; a[c][2] = e2 * inv;
            }
#pragma unroll
            for (int co = 0; co < 3; co++)
#pragma unroll
                for (int d = 0; d < 3; d++) {
                    float mm = 0.f;
#pragma unroll
                    for (int c = 0; c < 3; c++) mm += proj_w[co * 3 + c] * a[c][d];
                    g_M[b][co * 3 + d] = mm;
                }
            g_cnt[b] = 0;   // reset for next graph replay
            __threadfence();
        }
    }
}

// ---------------------------------------------------------------------------
// k_out: R10-proven 4x4 patch version; reads g_M broadcast (L2-hot).
// ---------------------------------------------------------------------------
__global__ __launch_bounds__(NTH) void k_out(const float* __restrict__ x,
                                             const float* __restrict__ kC,
                                             const float* __restrict__ kD,
                                             const float* __restrict__ proj_b,
                                             float* __restrict__ out) {
    const int b = blockIdx.z;
    const int warp = threadIdx.x >> 5, lane = threadIdx.x & 31;
    const int wx0 = blockIdx.x * 128;
    const int px0 = wx0 + lane * 4;
    const int y0 = blockIdx.y * 32 + warp * 4;

    const float* __restrict__ xb = x + (size_t)b * 3 * N_PIX;

    const bool is_e = (lane == 0) | (lane == 31);
    const int ex = (lane == 0) ? wx0 - 1 : wx0 + 128;
    const bool ex_ok = (unsigned)ex < (unsigned)W_IMG;

    float cw[9], dw[27];
#pragma unroll
    for (int i = 0; i < 9; i++) cw[i] = kC[i];
#pragma unroll
    for (int i = 0; i < 27; i++) dw[i] = kD[i];

    float m[9];
#pragma unroll
    for (int i = 0; i < 9; i++) m[i] = g_M[b][i];
    const float b0 = proj_b[0], b1 = proj_b[1], b2 = proj_b[2];

    float a0[3][4], a1[3][4], a2[3][4];
#pragma unroll
    for (int c = 0; c < 3; c++)
#pragma unroll
        for (int j = 0; j < 4; j++) { a0[c][j] = a1[c][j] = a2[c][j] = 0.f; }

#pragma unroll
    for (int iy = 0; iy < 6; iy++) {
        const int yin = y0 + iy - 1;
        const bool yok = (unsigned)yin < (unsigned)W_IMG;

        float hm[3][4];
#pragma unroll
        for (int c = 0; c < 3; c++)
#pragma unroll
            for (int j = 0; j < 4; j++) hm[c][j] = 0.f;

        if (yok) {
            const float4* p4 = (const float4*)(xb + (size_t)(yin * W_IMG + px0) * 3);
            float4 v0 = p4[0], v1 = p4[1], v2 = p4[2];
            float g[4][3] = {{v0.x, v0.y, v0.z}, {v0.w, v1.x, v1.y},
                             {v1.z, v1.w, v2.x}, {v2.y, v2.z, v2.w}};
#pragma unroll
            for (int j = 0; j < 4; j++)
#pragma unroll
                for (int c = 0; c < 3; c++)
                    hm[c][j] = cw[c * 3] * g[j][0] + cw[c * 3 + 1] * g[j][1] + cw[c * 3 + 2] * g[j][2];
        }
        float he[3] = {0.f, 0.f, 0.f};
        if (yok && is_e && ex_ok) {
            const float* pe = xb + (size_t)(yin * W_IMG + ex) * 3;
            float g0 = pe[0], g1 = pe[1], g2 = pe[2];
#pragma unroll
            for (int c = 0; c < 3; c++)
                he[c] = cw[c * 3] * g0 + cw[c * 3 + 1] * g1 + cw[c * 3 + 2] * g2;
        }
        float hl[3], hr[3];
#pragma unroll
        for (int c = 0; c < 3; c++) {
            hl[c] = __shfl_up_sync(0xffffffffu, hm[c][3], 1);
            hr[c] = __shfl_down_sync(0xffffffffu, hm[c][0], 1);
            if (lane == 0) hl[c] = he[c];
            if (lane == 31) hr[c] = he[c];
        }
#pragma unroll
        for (int c = 0; c < 3; c++)
#pragma unroll
            for (int j = 0; j < 4; j++) {
                float L = j ? hm[c][j - 1] : hl[c];
                float M_ = hm[c][j];
                float R = (j < 3) ? hm[c][j + 1] : hr[c];
                a0[c][j] += dw[c * 9 + 6] * L + dw[c * 9 + 7] * M_ + dw[c * 9 + 8] * R;
                a1[c][j] += dw[c * 9 + 3] * L + dw[c * 9 + 4] * M_ + dw[c * 9 + 5] * R;
                a2[c][j] += dw[c * 9 + 0] * L + dw[c * 9 + 1] * M_ + dw[c * 9 + 2] * R;
            }
        if (iy >= 2) {
            const int yout = y0 + iy - 2;
            float o[12];
#pragma unroll
            for (int j = 0; j < 4; j++) {
                float k0 = a0[0][j], k1 = a0[1][j], k2 = a0[2][j];
                o[j * 3 + 0] = m[0] * k0 + m[1] * k1 + m[2] * k2 + b0;
                o[j * 3 + 1] = m[3] * k0 + m[4] * k1 + m[5] * k2 + b1;
                o[j * 3 + 2] = m[6] * k0 + m[7] * k1 + m[8] * k2 + b2;
            }
            float4* q4 = (float4*)(out + ((size_t)b * N_PIX + (size_t)yout * W_IMG + px0) * 3);
            q4[0] = make_float4(o[0], o[1], o[2], o[3]);
            q4[1] = make_float4(o[4], o[5], o[6], o[7]);
            q4[2] = make_float4(o[8], o[9], o[10], o[11]);
        }
#pragma unroll
        for (int c = 0; c < 3; c++)
#pragma unroll
            for (int j = 0; j < 4; j++) {
                a0[c][j] = a1[c][j];
                a1[c][j] = a2[c][j];
                a2[c][j] = 0.f;
            }
    }
}

extern "C" void kernel_launch(void* const* d_in, const int* in_sizes, int n_in,
                              void* d_out, int out_size) {
    const float* x     = (const float*)d_in[0];
    const float* fhigh = (const float*)d_in[1];
    const float* qCw   = (const float*)d_in[2];
    const float* qdw   = (const float*)d_in[3];
    const float* kCw   = (const float*)d_in[4];
    const float* kdw   = (const float*)d_in[5];
    const float* projw = (const float*)d_in[6];
    const float* projb = (const float*)d_in[7];
    const float* temp  = (const float*)d_in[8];
    float* out = (float*)d_out;

    int B = in_sizes[0] / (N_PIX * 3);
    if (B > MAXB) B = MAXB;

    dim3 gridS(8, 4, B);                       // 32 blocks per batch
    k_stats<<<gridS, NTH>>>(x, fhigh, qCw, qdw, kCw, kdw, projw, temp);
    dim3 gridO(W_IMG / 128, W_IMG / 32, B);    // 256 blocks per batch
    k_out<<<gridO, NTH>>>(x, kCw, kdw, projb, out);
}

// round 12
// speedup vs baseline: 1.1129x; 1.0327x over previous
#include <cuda_runtime.h>
#include <math.h>

#define W_IMG 1024
#define N_PIX (W_IMG * W_IMG)
#define MAXB 8
#define NTH 256
#define NBLK_STAT 256   // 8 x 32 blocks per batch

// per-block partial stats: [b][block][16]
// [0..2]=sum q_c^2, [3..5]=sum k_c^2, [6..14]=sum q_c*k_d
__device__ float g_part[MAXB][NBLK_STAT][16];
__device__ float g_M[MAXB][12];
__device__ int   g_cnt[MAXB];   // zero-init at load; finalizer resets each launch

// ---------------------------------------------------------------------------
// k_stats: R6-proven 4x4 patch per thread (register kout). K path first,
// then Q path accumulating the 15 stats. Per-block partials + last-block
// finalize computing g_M (no k_zero launch, no atomicAdd contention).
// ---------------------------------------------------------------------------
__global__ __launch_bounds__(NTH) void k_stats(const float* __restrict__ x,
                                               const float* __restrict__ fhigh,
                                               const float* __restrict__ qC,
                                               const float* __restrict__ qD,
                                               const float* __restrict__ kC,
                                               const float* __restrict__ kD,
                                               const float* __restrict__ proj_w,
                                               const float* __restrict__ temp) {
    __shared__ float red[NTH / 32][15];
    __shared__ int sflag;

    const int tid = threadIdx.x;
    const int b = blockIdx.z;
    const int warp = tid >> 5, lane = tid & 31;
    const int wx0 = blockIdx.x * 128;
    const int px0 = wx0 + lane * 4;
    const int y0 = blockIdx.y * 32 + warp * 4;

    const float* __restrict__ xb = x + (size_t)b * 3 * N_PIX;
    const float* __restrict__ fb = fhigh + (size_t)b * 3 * N_PIX;

    const bool is_e = (lane == 0) | (lane == 31);
    const int ex = (lane == 0) ? wx0 - 1 : wx0 + 128;
    const bool ex_ok = (unsigned)ex < (unsigned)W_IMG;

    float p[15];
#pragma unroll
    for (int i = 0; i < 15; i++) p[i] = 0.f;

    float kout[3][4][4];  // [ch][row][j]

    // ================= K path (input x, channels-last) =================
    {
        float cw[9], dw[27];
#pragma unroll
        for (int i = 0; i < 9; i++) cw[i] = kC[i];
#pragma unroll
        for (int i = 0; i < 27; i++) dw[i] = kD[i];

        float a0[3][4], a1[3][4], a2[3][4];
#pragma unroll
        for (int c = 0; c < 3; c++)
#pragma unroll
            for (int j = 0; j < 4; j++) { a0[c][j] = a1[c][j] = a2[c][j] = 0.f; }

#pragma unroll
        for (int iy = 0; iy < 6; iy++) {
            const int yin = y0 + iy - 1;
            const bool yok = (unsigned)yin < (unsigned)W_IMG;

            float hm[3][4];
#pragma unroll
            for (int c = 0; c < 3; c++)
#pragma unroll
                for (int j = 0; j < 4; j++) hm[c][j] = 0.f;

            if (yok) {
                const float4* p4 = (const float4*)(xb + (size_t)(yin * W_IMG + px0) * 3);
                float4 v0 = p4[0], v1 = p4[1], v2 = p4[2];
                float g[4][3] = {{v0.x, v0.y, v0.z}, {v0.w, v1.x, v1.y},
                                 {v1.z, v1.w, v2.x}, {v2.y, v2.z, v2.w}};
#pragma unroll
                for (int j = 0; j < 4; j++)
#pragma unroll
                    for (int c = 0; c < 3; c++)
                        hm[c][j] = cw[c * 3] * g[j][0] + cw[c * 3 + 1] * g[j][1] + cw[c * 3 + 2] * g[j][2];
            }
            float he[3] = {0.f, 0.f, 0.f};
            if (yok && is_e && ex_ok) {
                const float* pe = xb + (size_t)(yin * W_IMG + ex) * 3;
                float g0 = pe[0], g1 = pe[1], g2 = pe[2];
#pragma unroll
                for (int c = 0; c < 3; c++)
                    he[c] = cw[c * 3] * g0 + cw[c * 3 + 1] * g1 + cw[c * 3 + 2] * g2;
            }
            float hl[3], hr[3];
#pragma unroll
            for (int c = 0; c < 3; c++) {
                hl[c] = __shfl_up_sync(0xffffffffu, hm[c][3], 1);
                hr[c] = __shfl_down_sync(0xffffffffu, hm[c][0], 1);
                if (lane == 0) hl[c] = he[c];
                if (lane == 31) hr[c] = he[c];
            }
#pragma unroll
            for (int c = 0; c < 3; c++)
#pragma unroll
                for (int j = 0; j < 4; j++) {
                    float L = j ? hm[c][j - 1] : hl[c];
                    float M_ = hm[c][j];
                    float R = (j < 3) ? hm[c][j + 1] : hr[c];
                    a0[c][j] += dw[c * 9 + 6] * L + dw[c * 9 + 7] * M_ + dw[c * 9 + 8] * R;
                    a1[c][j] += dw[c * 9 + 3] * L + dw[c * 9 + 4] * M_ + dw[c * 9 + 5] * R;
                    a2[c][j] += dw[c * 9 + 0] * L + dw[c * 9 + 1] * M_ + dw[c * 9 + 2] * R;
                }
            if (iy >= 2) {
                const int r = iy - 2;
#pragma unroll
                for (int c = 0; c < 3; c++)
#pragma unroll
                    for (int j = 0; j < 4; j++) {
                        float v = a0[c][j];
                        kout[c][r][j] = v;
                        p[3 + c] += v * v;
                    }
            }
#pragma unroll
            for (int c = 0; c < 3; c++)
#pragma unroll
                for (int j = 0; j < 4; j++) {
                    a0[c][j] = a1[c][j];
                    a1[c][j] = a2[c][j];
                    a2[c][j] = 0.f;
                }
        }
    }

    // ================= Q path (input fhigh, planar) =================
    {
        float cw[9], dw[27];
#pragma unroll
        for (int i = 0; i < 9; i++) cw[i] = qC[i];
#pragma unroll
        for (int i = 0; i < 27; i++) dw[i] = qD[i];

        float a0[3][4], a1[3][4], a2[3][4];
#pragma unroll
        for (int c = 0; c < 3; c++)
#pragma unroll
            for (int j = 0; j < 4; j++) { a0[c][j] = a1[c][j] = a2[c][j] = 0.f; }

#pragma unroll
        for (int iy = 0; iy < 6; iy++) {
            const int yin = y0 + iy - 1;
            const bool yok = (unsigned)yin < (unsigned)W_IMG;

            float hm[3][4];
#pragma unroll
            for (int c = 0; c < 3; c++)
#pragma unroll
                for (int j = 0; j < 4; j++) hm[c][j] = 0.f;

            if (yok) {
                const size_t o = (size_t)yin * W_IMG + px0;
                float4 f0 = *(const float4*)(fb + o);
                float4 f1 = *(const float4*)(fb + o + N_PIX);
                float4 f2 = *(const float4*)(fb + o + 2 * N_PIX);
                float g[4][3] = {{f0.x, f1.x, f2.x}, {f0.y, f1.y, f2.y},
                                 {f0.z, f1.z, f2.z}, {f0.w, f1.w, f2.w}};
#pragma unroll
                for (int j = 0; j < 4; j++)
#pragma unroll
                    for (int c = 0; c < 3; c++)
                        hm[c][j] = cw[c * 3] * g[j][0] + cw[c * 3 + 1] * g[j][1] + cw[c * 3 + 2] * g[j][2];
            }
            float he[3] = {0.f, 0.f, 0.f};
            if (yok && is_e && ex_ok) {
                const size_t o = (size_t)yin * W_IMG + ex;
                float g0 = fb[o], g1 = fb[o + N_PIX], g2 = fb[o + 2 * N_PIX];
#pragma unroll
                for (int c = 0; c < 3; c++)
                    he[c] = cw[c * 3] * g0 + cw[c * 3 + 1] * g1 + cw[c * 3 + 2] * g2;
            }
            float hl[3], hr[3];
#pragma unroll
            for (int c = 0; c < 3; c++) {
                hl[c] = __shfl_up_sync(0xffffffffu, hm[c][3], 1);
                hr[c] = __shfl_down_sync(0xffffffffu, hm[c][0], 1);
                if (lane == 0) hl[c] = he[c];
                if (lane == 31) hr[c] = he[c];
            }
#pragma unroll
            for (int c = 0; c < 3; c++)
#pragma unroll
                for (int j = 0; j < 4; j++) {
                    float L = j ? hm[c][j - 1] : hl[c];
                    float M_ = hm[c][j];
                    float R = (j < 3) ? hm[c][j + 1] : hr[c];
                    a0[c][j] += dw[c * 9 + 6] * L + dw[c * 9 + 7] * M_ + dw[c * 9 + 8] * R;
                    a1[c][j] += dw[c * 9 + 3] * L + dw[c * 9 + 4] * M_ + dw[c * 9 + 5] * R;
                    a2[c][j] += dw[c * 9 + 0] * L + dw[c * 9 + 1] * M_ + dw[c * 9 + 2] * R;
                }
            if (iy >= 2) {
                const int r = iy - 2;
#pragma unroll
                for (int c = 0; c < 3; c++)
#pragma unroll
                    for (int j = 0; j < 4; j++) {
                        float q = a0[c][j];
                        p[c] += q * q;
#pragma unroll
                        for (int d = 0; d < 3; d++)
                            p[6 + c * 3 + d] += q * kout[d][r][j];
                    }
            }
#pragma unroll
            for (int c = 0; c < 3; c++)
#pragma unroll
                for (int j = 0; j < 4; j++) {
                    a0[c][j] = a1[c][j];
                    a1[c][j] = a2[c][j];
                    a2[c][j] = 0.f;
                }
        }
    }

    // block reduce -> per-block partial
#pragma unroll
    for (int i = 0; i < 15; i++)
#pragma unroll
        for (int o = 16; o; o >>= 1)
            p[i] += __shfl_down_sync(0xffffffffu, p[i], o);
    if (lane == 0) {
#pragma unroll
        for (int i = 0; i < 15; i++) red[warp][i] = p[i];
    }
    __syncthreads();
    const int bi = blockIdx.y * 8 + blockIdx.x;
    if (tid < 15) {
        float t = 0.f;
#pragma unroll
        for (int w2 = 0; w2 < NTH / 32; w2++) t += red[w2][tid];
        g_part[b][bi][tid] = t;
    }
    __syncthreads();

    // --- last-block finalize: reduce 256 partials, compute g_M ---
    if (tid == 0) {
        __threadfence();
        int v = atomicAdd(&g_cnt[b], 1);
        sflag = (v == NBLK_STAT - 1);
    }
    __syncthreads();
    if (sflag) {
        __threadfence();
        float q[15];
        const float4* row = (const float4*)g_part[b][tid];
        float4 v0 = row[0], v1 = row[1], v2 = row[2], v3 = row[3];
        q[0] = v0.x;  q[1] = v0.y;  q[2] = v0.z;  q[3] = v0.w;
        q[4] = v1.x;  q[5] = v1.y;  q[6] = v1.z;  q[7] = v1.w;
        q[8] = v2.x;  q[9] = v2.y;  q[10] = v2.z; q[11] = v2.w;
        q[12] = v3.x; q[13] = v3.y; q[14] = v3.z;
#pragma unroll
        for (int i = 0; i < 15; i++)
#pragma unroll
            for (int o = 16; o; o >>= 1)
                q[i] += __shfl_down_sync(0xffffffffu, q[i], o);
        if (lane == 0) {
#pragma unroll
            for (int i = 0; i < 15; i++) red[warp][i] = q[i];
        }
        __syncthreads();
        if (tid == 0) {
            float ss[15];
#pragma unroll
            for (int i = 0; i < 15; i++) {
                float t = 0.f;
#pragma unroll
                for (int w2 = 0; w2 < NTH / 32; w2++) t += red[w2][i];
                ss[i] = t;
            }
            float T = temp[0];
            float nq[3], nk[3];
#pragma unroll
            for (int c = 0; c < 3; c++) {
                nq[c] = fmaxf(sqrtf(ss[c]), 1e-12f);
                nk[c] = fmaxf(sqrtf(ss[3 + c]), 1e-12f);
            }
            float a[3][3];
#pragma unroll
            for (int c = 0; c < 3; c++)
#pragma unroll
                for (int d = 0; d < 3; d++)
                    a[c][d] = ss[6 + c * 3 + d] / (nq[c] * nk[d]) * T;
#pragma unroll
            for (int c = 0; c < 3; c++) {
                float mx = fmaxf(a[c][0], fmaxf(a[c][1], a[c][2]));
                float e0 = expf(a[c][0] - mx);
                float e1 = expf(a[c][1] - mx);
                float e2 = expf(a[c][2] - mx);
                float inv = 1.f / (e0 + e1 + e2);
                a[c][0] = e0 * inv; a[c][1] = e1 * inv; a[c][2] = e2 * inv;
            }
#pragma unroll
            for (int co = 0; co < 3; co++)
#pragma unroll
                for (int d = 0; d < 3; d++) {
                    float mm = 0.f;
#pragma unroll
                    for (int c = 0; c < 3; c++) mm += proj_w[co * 3 + c] * a[c][d];
                    g_M[b][co * 3 + d] = mm;
                }
            g_cnt[b] = 0;   // reset for next graph replay
            __threadfence();
        }
    }
}

// ---------------------------------------------------------------------------
// k_out: R10/R11-proven 4x4 patch version; reads g_M broadcast (L2-hot).
// ---------------------------------------------------------------------------
__global__ __launch_bounds__(NTH) void k_out(const float* __restrict__ x,
                                             const float* __restrict__ kC,
                                             const float* __restrict__ kD,
                                             const float* __restrict__ proj_b,
                                             float* __restrict__ out) {
    const int b = blockIdx.z;
    const int warp = threadIdx.x >> 5, lane = threadIdx.x & 31;
    const int wx0 = blockIdx.x * 128;
    const int px0 = wx0 + lane * 4;
    const int y0 = blockIdx.y * 32 + warp * 4;

    const float* __restrict__ xb = x + (size_t)b * 3 * N_PIX;

    const bool is_e = (lane == 0) | (lane == 31);
    const int ex = (lane == 0) ? wx0 - 1 : wx0 + 128;
    const bool ex_ok = (unsigned)ex < (unsigned)W_IMG;

    float cw[9], dw[27];
#pragma unroll
    for (int i = 0; i < 9; i++) cw[i] = kC[i];
#pragma unroll
    for (int i = 0; i < 27; i++) dw[i] = kD[i];

    float m[9];
#pragma unroll
    for (int i = 0; i < 9; i++) m[i] = g_M[b][i];
    const float b0 = proj_b[0], b1 = proj_b[1], b2 = proj_b[2];

    float a0[3][4], a1[3][4], a2[3][4];
#pragma unroll
    for (int c = 0; c < 3; c++)
#pragma unroll
        for (int j = 0; j < 4; j++) { a0[c][j] = a1[c][j] = a2[c][j] = 0.f; }

#pragma unroll
    for (int iy = 0; iy < 6; iy++) {
        const int yin = y0 + iy - 1;
        const bool yok = (unsigned)yin < (unsigned)W_IMG;

        float hm[3][4];
#pragma unroll
        for (int c = 0; c < 3; c++)
#pragma unroll
            for (int j = 0; j < 4; j++) hm[c][j] = 0.f;

        if (yok) {
            const float4* p4 = (const float4*)(xb + (size_t)(yin * W_IMG + px0) * 3);
            float4 v0 = p4[0], v1 = p4[1], v2 = p4[2];
            float g[4][3] = {{v0.x, v0.y, v0.z}, {v0.w, v1.x, v1.y},
                             {v1.z, v1.w, v2.x}, {v2.y, v2.z, v2.w}};
#pragma unroll
            for (int j = 0; j < 4; j++)
#pragma unroll
                for (int c = 0; c < 3; c++)
                    hm[c][j] = cw[c * 3] * g[j][0] + cw[c * 3 + 1] * g[j][1] + cw[c * 3 + 2] * g[j][2];
        }
        float he[3] = {0.f, 0.f, 0.f};
        if (yok && is_e && ex_ok) {
            const float* pe = xb + (size_t)(yin * W_IMG + ex) * 3;
            float g0 = pe[0], g1 = pe[1], g2 = pe[2];
#pragma unroll
            for (int c = 0; c < 3; c++)
                he[c] = cw[c * 3] * g0 + cw[c * 3 + 1] * g1 + cw[c * 3 + 2] * g2;
        }
        float hl[3], hr[3];
#pragma unroll
        for (int c = 0; c < 3; c++) {
            hl[c] = __shfl_up_sync(0xffffffffu, hm[c][3], 1);
            hr[c] = __shfl_down_sync(0xffffffffu, hm[c][0], 1);
            if (lane == 0) hl[c] = he[c];
            if (lane == 31) hr[c] = he[c];
        }
#pragma unroll
        for (int c = 0; c < 3; c++)
#pragma unroll
            for (int j = 0; j < 4; j++) {
                float L = j ? hm[c][j - 1] : hl[c];
                float M_ = hm[c][j];
                float R = (j < 3) ? hm[c][j + 1] : hr[c];
                a0[c][j] += dw[c * 9 + 6] * L + dw[c * 9 + 7] * M_ + dw[c * 9 + 8] * R;
                a1[c][j] += dw[c * 9 + 3] * L + dw[c * 9 + 4] * M_ + dw[c * 9 + 5] * R;
                a2[c][j] += dw[c * 9 + 0] * L + dw[c * 9 + 1] * M_ + dw[c * 9 + 2] * R;
            }
        if (iy >= 2) {
            const int yout = y0 + iy - 2;
            float o[12];
#pragma unroll
            for (int j = 0; j < 4; j++) {
                float k0 = a0[0][j], k1 = a0[1][j], k2 = a0[2][j];
                o[j * 3 + 0] = m[0] * k0 + m[1] * k1 + m[2] * k2 + b0;
                o[j * 3 + 1] = m[3] * k0 + m[4] * k1 + m[5] * k2 + b1;
                o[j * 3 + 2] = m[6] * k0 + m[7] * k1 + m[8] * k2 + b2;
            }
            float4* q4 = (float4*)(out + ((size_t)b * N_PIX + (size_t)yout * W_IMG + px0) * 3);
            q4[0] = make_float4(o[0], o[1], o[2], o[3]);
            q4[1] = make_float4(o[4], o[5], o[6], o[7]);
            q4[2] = make_float4(o[8], o[9], o[10], o[11]);
        }
#pragma unroll
        for (int c = 0; c < 3; c++)
#pragma unroll
            for (int j = 0; j < 4; j++) {
                a0[c][j] = a1[c][j];
                a1[c][j] = a2[c][j];
                a2[c][j] = 0.f;
            }
    }
}

extern "C" void kernel_launch(void* const* d_in, const int* in_sizes, int n_in,
                              void* d_out, int out_size) {
    const float* x     = (const float*)d_in[0];
    const float* fhigh = (const float*)d_in[1];
    const float* qCw   = (const float*)d_in[2];
    const float* qdw   = (const float*)d_in[3];
    const float* kCw   = (const float*)d_in[4];
    const float* kdw   = (const float*)d_in[5];
    const float* projw = (const float*)d_in[6];
    const float* projb = (const float*)d_in[7];
    const float* temp  = (const float*)d_in[8];
    float* out = (float*)d_out;

    int B = in_sizes[0] / (N_PIX * 3);
    if (B > MAXB) B = MAXB;

    dim3 gridS(W_IMG / 128, W_IMG / 32, B);   // 8 x 32 = 256 blocks per batch
    k_stats<<<gridS, NTH>>>(x, fhigh, qCw, qdw, kCw, kdw, projw, temp);
    dim3 gridO(W_IMG / 128, W_IMG / 32, B);   // 256 blocks per batch
    k_out<<<gridO, NTH>>>(x, kCw, kdw, projb, out);
}